// round 1
// baseline (speedup 1.0000x reference)
#include <cuda_runtime.h>
#include <math.h>

#define N_LABELS 30000
#define HIDDEN   1024
#define BATCH    256
#define N_EDGES  (N_LABELS - 1)

// Accumulators + converted int32 indices (device globals: no allocation allowed).
__device__ double g_acc[3];          // 0: bce_sum, 1: 0.5*rec_sum, 2: prob_sum
__device__ int g_par[N_EDGES];
__device__ int g_chi[N_EDGES];

// ---------------------------------------------------------------------------
// Init: zero accumulators, convert indices (auto-detect int64 vs int32).
// If the buffer really holds int64 values in [0, N_LABELS), every int64 read
// is small; if it holds int32, the int64 reinterpretation has a nonzero high
// word with overwhelming probability across 64 samples.
// ---------------------------------------------------------------------------
__global__ void init_kernel(const void* __restrict__ par_raw,
                            const void* __restrict__ chi_raw) {
    __shared__ int s_is32;
    if (threadIdx.x == 0) s_is32 = 0;
    __syncthreads();
    if (threadIdx.x < 64) {
        long long v = ((const long long*)par_raw)[threadIdx.x];
        if (v < 0 || v >= (long long)N_LABELS) atomicOr(&s_is32, 1);
    }
    __syncthreads();
    const bool is32 = (s_is32 != 0);

    int i = blockIdx.x * blockDim.x + threadIdx.x;
    if (i < N_EDGES) {
        if (is32) {
            g_par[i] = ((const int*)par_raw)[i];
            g_chi[i] = ((const int*)chi_raw)[i];
        } else {
            g_par[i] = (int)((const long long*)par_raw)[i];
            g_chi[i] = (int)((const long long*)chi_raw)[i];
        }
    }
    if (blockIdx.x == 0 && threadIdx.x < 3) g_acc[threadIdx.x] = 0.0;
}

// ---------------------------------------------------------------------------
// Block reduction helper (caller must __syncthreads() between reuses of red).
// ---------------------------------------------------------------------------
__device__ __forceinline__ float block_reduce(float v, float* red) {
    const int lane = threadIdx.x & 31;
    const int wid  = threadIdx.x >> 5;
#pragma unroll
    for (int o = 16; o; o >>= 1) v += __shfl_down_sync(0xffffffffu, v, o);
    if (lane == 0) red[wid] = v;
    __syncthreads();
    float r = 0.f;
    if (wid == 0) {
        const int nw = (blockDim.x + 31) >> 5;
        r = (lane < nw) ? red[lane] : 0.f;
#pragma unroll
        for (int o = 16; o; o >>= 1) r += __shfl_down_sync(0xffffffffu, r, o);
    }
    return r;  // valid on thread 0
}

// ---------------------------------------------------------------------------
// Fused BCE + proba-regularization. One CTA per batch row:
//   pass 1: stream logits/targets (float4), accumulate BCE, write sigmoid row
//           into shared memory (120 KB dynamic smem).
//   pass 2: gather edge pairs from SMEM, accumulate relu(s_child - s_parent).
// ---------------------------------------------------------------------------
__global__ void __launch_bounds__(512, 1)
bce_prob_kernel(const float* __restrict__ logits,
                const float* __restrict__ targets) {
    extern __shared__ float s_prob[];        // N_LABELS floats
    __shared__ float s_red[32];

    const int b = blockIdx.x;
    const float4* __restrict__ l4 = (const float4*)(logits + (size_t)b * N_LABELS);
    const float4* __restrict__ t4 = (const float4*)(targets + (size_t)b * N_LABELS);
    float4* sp4 = (float4*)s_prob;

    float bce = 0.f;
    for (int i = threadIdx.x; i < N_LABELS / 4; i += blockDim.x) {
        float4 l = l4[i];
        float4 t = t4[i];
        float4 s;
        {
            float x = l.x;
            bce += fmaxf(x, 0.f) + log1pf(__expf(-fabsf(x))) - x * t.x;
            s.x = 1.f / (1.f + __expf(-x));
        }
        {
            float x = l.y;
            bce += fmaxf(x, 0.f) + log1pf(__expf(-fabsf(x))) - x * t.y;
            s.y = 1.f / (1.f + __expf(-x));
        }
        {
            float x = l.z;
            bce += fmaxf(x, 0.f) + log1pf(__expf(-fabsf(x))) - x * t.z;
            s.z = 1.f / (1.f + __expf(-x));
        }
        {
            float x = l.w;
            bce += fmaxf(x, 0.f) + log1pf(__expf(-fabsf(x))) - x * t.w;
            s.w = 1.f / (1.f + __expf(-x));
        }
        sp4[i] = s;
    }
    __syncthreads();

    float pr = 0.f;
    for (int e = threadIdx.x; e < N_EDGES; e += blockDim.x) {
        float d = s_prob[g_chi[e]] - s_prob[g_par[e]];
        pr += fmaxf(d, 0.f);
    }

    float tb = block_reduce(bce, s_red);
    __syncthreads();
    float tp = block_reduce(pr, s_red);
    if (threadIdx.x == 0) {
        atomicAdd(&g_acc[0], (double)tb);
        atomicAdd(&g_acc[2], (double)tp);
    }
}

// ---------------------------------------------------------------------------
// Recursive regularization: 0.5 * sum_e ||params[par[e]] - params[chi[e]]||^2.
// One edge per block-iteration; 256 threads each read one float4 per row
// (4 KB coalesced per row). Grid-stride keeps the atomic count at ~4K.
// ---------------------------------------------------------------------------
__global__ void __launch_bounds__(256)
rec_kernel(const float* __restrict__ params) {
    __shared__ float s_red[32];
    float acc = 0.f;
    for (int e = blockIdx.x; e < N_EDGES; e += gridDim.x) {
        const float4* __restrict__ p =
            (const float4*)(params + (size_t)g_par[e] * HIDDEN) + threadIdx.x;
        const float4* __restrict__ c =
            (const float4*)(params + (size_t)g_chi[e] * HIDDEN) + threadIdx.x;
        float4 a = *p;
        float4 bb = *c;
        float dx = a.x - bb.x, dy = a.y - bb.y, dz = a.z - bb.z, dw = a.w - bb.w;
        acc = fmaf(dx, dx, fmaf(dy, dy, fmaf(dz, dz, fmaf(dw, dw, acc))));
    }
    float t = block_reduce(acc, s_red);
    if (threadIdx.x == 0) atomicAdd(&g_acc[1], 0.5 * (double)t);
}

// ---------------------------------------------------------------------------
// Combine.
// ---------------------------------------------------------------------------
__global__ void final_kernel(float* __restrict__ out) {
    out[0] = (float)(g_acc[0] / ((double)BATCH * (double)N_LABELS)
                     + 1e-4 * g_acc[1] + 1e-4 * g_acc[2]);
}

// ---------------------------------------------------------------------------
// Launch. Inputs per metadata order: logits, targets, params, parent_idx,
// child_idx. Output: scalar float loss.
// ---------------------------------------------------------------------------
extern "C" void kernel_launch(void* const* d_in, const int* in_sizes, int n_in,
                              void* d_out, int out_size) {
    const float* logits  = (const float*)d_in[0];
    const float* targets = (const float*)d_in[1];
    const float* params  = (const float*)d_in[2];
    const void*  par     = d_in[3];
    const void*  chi     = d_in[4];
    float* out = (float*)d_out;

    (void)in_sizes; (void)n_in; (void)out_size;

    // 120 KB dynamic smem for the sigmoid row cache (idempotent, non-stream API).
    cudaFuncSetAttribute(bce_prob_kernel,
                         cudaFuncAttributeMaxDynamicSharedMemorySize,
                         N_LABELS * (int)sizeof(float));

    init_kernel<<<(N_EDGES + 255) / 256, 256>>>(par, chi);
    bce_prob_kernel<<<BATCH, 512, N_LABELS * sizeof(float)>>>(logits, targets);
    rec_kernel<<<4096, 256>>>(params);
    final_kernel<<<1, 1>>>(out);
}

// round 2
// speedup vs baseline: 1.0902x; 1.0902x over previous
#include <cuda_runtime.h>
#include <cuda_fp16.h>
#include <math.h>

#define N_LABELS 30000
#define HIDDEN   1024
#define BATCH    256
#define N_EDGES  (N_LABELS - 1)

#define BCE_BLOCKS (BATCH / 2)          // 128 CTAs, 2 batch rows each
#define REC_BLOCKS 464
#define GRID       (BCE_BLOCKS + REC_BLOCKS)   // 592
#define NTHREADS   512
#define SMEM_BYTES (2 * N_LABELS * (int)sizeof(__half))   // 120000 B

// Device globals (no allocation allowed).
__device__ int2   g_edge[N_EDGES];      // packed (parent, child) as int32
__device__ double g_part[GRID][3];      // per-block partials: bce, rec, prob
__device__ unsigned int g_ticket;       // zero at load; reset by final block

// ---------------------------------------------------------------------------
// Init: convert indices (auto-detect int64 vs int32) into packed int2.
// ---------------------------------------------------------------------------
__global__ void init_kernel(const void* __restrict__ par_raw,
                            const void* __restrict__ chi_raw) {
    __shared__ int s_is32;
    if (threadIdx.x == 0) s_is32 = 0;
    __syncthreads();
    if (threadIdx.x < 64) {
        long long v = ((const long long*)par_raw)[threadIdx.x];
        if (v < 0 || v >= (long long)N_LABELS) atomicOr(&s_is32, 1);
    }
    __syncthreads();
    const bool is32 = (s_is32 != 0);

    int i = blockIdx.x * blockDim.x + threadIdx.x;
    if (i < N_EDGES) {
        int p, c;
        if (is32) {
            p = ((const int*)par_raw)[i];
            c = ((const int*)chi_raw)[i];
        } else {
            p = (int)((const long long*)par_raw)[i];
            c = (int)((const long long*)chi_raw)[i];
        }
        g_edge[i] = make_int2(p, c);
    }
}

// ---------------------------------------------------------------------------
// Reductions.
// ---------------------------------------------------------------------------
__device__ __forceinline__ float block_reduce_f(float v, float* red) {
    const int lane = threadIdx.x & 31;
    const int wid  = threadIdx.x >> 5;
#pragma unroll
    for (int o = 16; o; o >>= 1) v += __shfl_down_sync(0xffffffffu, v, o);
    if (lane == 0) red[wid] = v;
    __syncthreads();
    float r = 0.f;
    if (wid == 0) {
        r = (lane < (NTHREADS / 32)) ? red[lane] : 0.f;
#pragma unroll
        for (int o = 16; o; o >>= 1) r += __shfl_down_sync(0xffffffffu, r, o);
    }
    return r;  // valid on thread 0
}

__device__ __forceinline__ double block_reduce_d(double v, double* red) {
    const int lane = threadIdx.x & 31;
    const int wid  = threadIdx.x >> 5;
#pragma unroll
    for (int o = 16; o; o >>= 1) v += __shfl_down_sync(0xffffffffu, v, o);
    if (lane == 0) red[wid] = v;
    __syncthreads();
    double r = 0.0;
    if (wid == 0) {
        r = (lane < (NTHREADS / 32)) ? red[lane] : 0.0;
#pragma unroll
        for (int o = 16; o; o >>= 1) r += __shfl_down_sync(0xffffffffu, r, o);
    }
    return r;  // valid on thread 0
}

// ---------------------------------------------------------------------------
// Fused mega kernel.
//   blocks [0, BCE_BLOCKS):  BCE + prob-reg over 2 batch rows (fp16 smem cache)
//   blocks [BCE_BLOCKS, GRID): rec-reg gather, 4-edge unroll for MLP
//   last block to finish: combines all partials and writes the scalar.
// ---------------------------------------------------------------------------
__global__ void __launch_bounds__(NTHREADS, 1)
mega_kernel(const float* __restrict__ logits,
            const float* __restrict__ targets,
            const float* __restrict__ params,
            float* __restrict__ out) {
    extern __shared__ __align__(16) char smem_raw[];
    __shared__ float  s_redf[32];
    __shared__ double s_redd[32];
    __shared__ unsigned s_tick;

    double p_bce = 0.0, p_rec = 0.0, p_pr = 0.0;
    const int tid = threadIdx.x;

    if (blockIdx.x < BCE_BLOCKS) {
        // ---------------- BCE + prob role ----------------
        __half* s0 = (__half*)smem_raw;                 // sigmoid row 2b
        __half* s1 = (__half*)smem_raw + N_LABELS;      // sigmoid row 2b+1
        const int b = blockIdx.x * 2;
        const float4* __restrict__ l0 = (const float4*)(logits  + (size_t)b * N_LABELS);
        const float4* __restrict__ t0 = (const float4*)(targets + (size_t)b * N_LABELS);
        const float4* __restrict__ l1 = (const float4*)(logits  + (size_t)(b + 1) * N_LABELS);
        const float4* __restrict__ t1 = (const float4*)(targets + (size_t)(b + 1) * N_LABELS);
        __half2* s0v = (__half2*)s0;
        __half2* s1v = (__half2*)s1;

        float bce = 0.f;
        for (int i = tid; i < N_LABELS / 4; i += NTHREADS) {
            float4 la = l0[i], ta = t0[i];
            float4 lb = l1[i], tb = t1[i];
            float sg[8];
            const float xs[8] = {la.x, la.y, la.z, la.w, lb.x, lb.y, lb.z, lb.w};
            const float ts[8] = {ta.x, ta.y, ta.z, ta.w, tb.x, tb.y, tb.z, tb.w};
#pragma unroll
            for (int k = 0; k < 8; k++) {
                float x = xs[k];
                float e = __expf(-fabsf(x));
                float r = __frcp_rn(1.f + e);          // sigmoid(|x|)
                // softplus(x) = max(x,0) + log1p(exp(-|x|)) = max(x,0) - log(r)
                bce += fmaxf(x, 0.f) - __logf(r) - x * ts[k];
                sg[k] = (x >= 0.f) ? r : (1.f - r);
            }
            s0v[2 * i]     = __floats2half2_rn(sg[0], sg[1]);
            s0v[2 * i + 1] = __floats2half2_rn(sg[2], sg[3]);
            s1v[2 * i]     = __floats2half2_rn(sg[4], sg[5]);
            s1v[2 * i + 1] = __floats2half2_rn(sg[6], sg[7]);
        }
        __syncthreads();

        float pr = 0.f;
        for (int e = tid; e < N_EDGES; e += NTHREADS) {
            int2 pc = g_edge[e];
            float d0 = __half2float(s0[pc.y]) - __half2float(s0[pc.x]);
            float d1 = __half2float(s1[pc.y]) - __half2float(s1[pc.x]);
            pr += fmaxf(d0, 0.f) + fmaxf(d1, 0.f);
        }

        float tb2 = block_reduce_f(bce, s_redf);
        __syncthreads();
        float tp = block_reduce_f(pr, s_redf);
        p_bce = (double)tb2;
        p_pr  = (double)tp;
    } else {
        // ---------------- rec role ----------------
        const int sub  = tid >> 8;           // two 256-thread sub-blocks
        const int stid = tid & 255;
        const int sid  = (blockIdx.x - BCE_BLOCKS) * 2 + sub;
        const int nsub = REC_BLOCKS * 2;

        float acc = 0.f;
        for (int e0 = sid * 4; e0 < N_EDGES; e0 += nsub * 4) {
            float4 a[4], b[4];
#pragma unroll
            for (int j = 0; j < 4; j++) {
                int e = e0 + j;
                int2 pc = (e < N_EDGES) ? g_edge[e] : make_int2(0, 0);
                a[j] = ((const float4*)(params + (size_t)pc.x * HIDDEN))[stid];
                b[j] = ((const float4*)(params + (size_t)pc.y * HIDDEN))[stid];
            }
#pragma unroll
            for (int j = 0; j < 4; j++) {
                // OOB j loads row 0 twice -> diff 0 -> contributes 0
                float dx = a[j].x - b[j].x, dy = a[j].y - b[j].y;
                float dz = a[j].z - b[j].z, dw = a[j].w - b[j].w;
                acc = fmaf(dx, dx, fmaf(dy, dy, fmaf(dz, dz, fmaf(dw, dw, acc))));
            }
        }
        float tr = block_reduce_f(acc, s_redf);
        p_rec = (double)tr;
    }

    // ---------------- partials + ticket ----------------
    if (tid == 0) {
        g_part[blockIdx.x][0] = p_bce;
        g_part[blockIdx.x][1] = p_rec;
        g_part[blockIdx.x][2] = p_pr;
        __threadfence();
        s_tick = atomicAdd(&g_ticket, 1u);
    }
    __syncthreads();

    if (s_tick == GRID - 1) {
        double sb = 0.0, sr = 0.0, sp = 0.0;
        for (int i = tid; i < GRID; i += NTHREADS) {
            sb += g_part[i][0];
            sr += g_part[i][1];
            sp += g_part[i][2];
        }
        double tb2 = block_reduce_d(sb, s_redd);
        __syncthreads();
        double tr = block_reduce_d(sr, s_redd);
        __syncthreads();
        double tp = block_reduce_d(sp, s_redd);
        if (tid == 0) {
            out[0] = (float)(tb2 / ((double)BATCH * (double)N_LABELS)
                             + 1e-4 * 0.5 * tr + 1e-4 * tp);
            g_ticket = 0u;   // reset for the next replay
        }
    }
}

// ---------------------------------------------------------------------------
// Launch. Inputs: logits, targets, params, parent_idx, child_idx. Output: f32.
// ---------------------------------------------------------------------------
extern "C" void kernel_launch(void* const* d_in, const int* in_sizes, int n_in,
                              void* d_out, int out_size) {
    const float* logits  = (const float*)d_in[0];
    const float* targets = (const float*)d_in[1];
    const float* params  = (const float*)d_in[2];
    const void*  par     = d_in[3];
    const void*  chi     = d_in[4];
    float* out = (float*)d_out;
    (void)in_sizes; (void)n_in; (void)out_size;

    cudaFuncSetAttribute(mega_kernel,
                         cudaFuncAttributeMaxDynamicSharedMemorySize, SMEM_BYTES);

    init_kernel<<<(N_EDGES + 255) / 256, 256>>>(par, chi);
    mega_kernel<<<GRID, NTHREADS, SMEM_BYTES>>>(logits, targets, params, out);
}